// round 15
// baseline (speedup 1.0000x reference)
#include <cuda_runtime.h>
#include <cuda_fp16.h>
#include <stdint.h>

#define HIDDEN   2048
#define NHEADS   32
#define SEQ      4096
#define NTOK     32768           // B * S
#define MCHUNK   16384           // tokens per pipeline chunk (2 chunks)

// ---------------- scratch (static device globals; no allocation) ----------------
__device__ __half g_x[(size_t)NTOK * HIDDEN];              // LN output fp16     (128 MB)
__device__ __half g_wt[(size_t)4 * HIDDEN * HIDDEN];       // wq^T|wk^T|wv^T|wo^T fp16 (32 MB)
__device__ __half g_qkv[(size_t)NTOK * 3 * HIDDEN];        // q|k|v per token    (402 MB)
__device__ __half g_attn[(size_t)NTOK * HIDDEN];           // attn out fp16      (128 MB)

// ---------------- stream/event infra (created at program init, before harness checkpoints) ----
struct Infra {
    cudaStream_t s2;
    cudaEvent_t eFork, eCvt, eQ0, eQ1, eA0, eA1;
    Infra() {
        cudaStreamCreateWithFlags(&s2, cudaStreamNonBlocking);
        cudaEventCreateWithFlags(&eFork, cudaEventDisableTiming);
        cudaEventCreateWithFlags(&eCvt, cudaEventDisableTiming);
        cudaEventCreateWithFlags(&eQ0,  cudaEventDisableTiming);
        cudaEventCreateWithFlags(&eQ1,  cudaEventDisableTiming);
        cudaEventCreateWithFlags(&eA0,  cudaEventDisableTiming);
        cudaEventCreateWithFlags(&eA1,  cudaEventDisableTiming);
    }
};
static Infra g_infra;

// ===================== PTX helpers (baseline sm_80+ features only) =====================
__device__ __forceinline__ uint32_t smem_u32(const void* p) {
    uint32_t a;
    asm("{ .reg .u64 t; cvta.to.shared.u64 t, %1; cvt.u32.u64 %0, t; }" : "=r"(a) : "l"(p));
    return a;
}
#define CP_ASYNC16(dst, src) \
    asm volatile("cp.async.cg.shared.global [%0], [%1], 16;" :: "r"(dst), "l"(src) : "memory")
#define CP_COMMIT() asm volatile("cp.async.commit_group;" ::: "memory")
#define CP_WAIT1()  asm volatile("cp.async.wait_group 1;" ::: "memory")

#define LDSM_X4(r0,r1,r2,r3, addr) \
    asm volatile("ldmatrix.sync.aligned.m8n8.x4.shared.b16 {%0,%1,%2,%3}, [%4];" \
        : "=r"(r0),"=r"(r1),"=r"(r2),"=r"(r3) : "r"(addr))

#define MMA16816(d, a0,a1,a2,a3, b0,b1) \
    asm volatile("mma.sync.aligned.m16n8k16.row.col.f32.f16.f16.f32 " \
        "{%0,%1,%2,%3}, {%4,%5,%6,%7}, {%8,%9}, {%0,%1,%2,%3};" \
        : "+f"((d)[0]),"+f"((d)[1]),"+f"((d)[2]),"+f"((d)[3]) \
        : "r"(a0),"r"(a1),"r"(a2),"r"(a3), "r"(b0),"r"(b1))

#define SWZ(off) ((off) ^ (((off) >> 3) & 0x70))

// ===================== LayerNorm -> fp16 =====================
__device__ __forceinline__ float warp_red(float v) {
    #pragma unroll
    for (int o = 16; o; o >>= 1) v += __shfl_xor_sync(0xffffffffu, v, o);
    return v;
}

__global__ __launch_bounds__(256) void ln_kernel(const float* __restrict__ hs,
                          const float* __restrict__ gamma,
                          const float* __restrict__ beta) {
    int t = blockIdx.x;
    int tid = threadIdx.x;
    const float4* row = (const float4*)(hs + (size_t)t * HIDDEN);
    float4 v0 = row[tid];
    float4 v1 = row[tid + 256];
    float s = v0.x + v0.y + v0.z + v0.w + v1.x + v1.y + v1.z + v1.w;
    float q = v0.x*v0.x + v0.y*v0.y + v0.z*v0.z + v0.w*v0.w
            + v1.x*v1.x + v1.y*v1.y + v1.z*v1.z + v1.w*v1.w;
    s = warp_red(s);
    q = warp_red(q);
    __shared__ float sh_s[8], sh_q[8];
    int w = tid >> 5, l = tid & 31;
    if (l == 0) { sh_s[w] = s; sh_q[w] = q; }
    __syncthreads();
    float st = 0.f, qt = 0.f;
    #pragma unroll
    for (int i = 0; i < 8; i++) { st += sh_s[i]; qt += sh_q[i]; }
    float mean = st * (1.0f / HIDDEN);
    float var  = qt * (1.0f / HIDDEN) - mean * mean;
    float rstd = rsqrtf(var + 1e-5f);

    const float4* g4 = (const float4*)gamma;
    const float4* b4 = (const float4*)beta;
    __half2* out = (__half2*)(g_x + (size_t)t * HIDDEN);
    {
        float4 g = g4[tid], b = b4[tid];
        out[2*tid]   = __floats2half2_rn((v0.x - mean)*rstd*g.x + b.x, (v0.y - mean)*rstd*g.y + b.y);
        out[2*tid+1] = __floats2half2_rn((v0.z - mean)*rstd*g.z + b.z, (v0.w - mean)*rstd*g.w + b.w);
    }
    {
        int i2 = tid + 256;
        float4 g = g4[i2], b = b4[i2];
        out[2*i2]   = __floats2half2_rn((v1.x - mean)*rstd*g.x + b.x, (v1.y - mean)*rstd*g.y + b.y);
        out[2*i2+1] = __floats2half2_rn((v1.z - mean)*rstd*g.z + b.z, (v1.w - mean)*rstd*g.w + b.w);
    }
}

// ===================== weight fp32 -> fp16, transposed (all 4 in one launch) =====================
__global__ __launch_bounds__(256) void cvt_t4_kernel(const float* __restrict__ w0, const float* __restrict__ w1,
                                                     const float* __restrict__ w2, const float* __restrict__ w3,
                                                     __half* __restrict__ obase) {
    const float* w = (blockIdx.z == 0) ? w0 : (blockIdx.z == 1) ? w1 : (blockIdx.z == 2) ? w2 : w3;
    __half* o = obase + (size_t)blockIdx.z * HIDDEN * HIDDEN;
    __shared__ float t[32][33];
    int bx = blockIdx.x * 32;   // n0
    int by = blockIdx.y * 32;   // k0
    int tx = threadIdx.x & 31, ty = threadIdx.x >> 5;
    #pragma unroll
    for (int r = 0; r < 32; r += 8)
        t[ty + r][tx] = w[(size_t)(by + ty + r) * HIDDEN + bx + tx];
    __syncthreads();
    #pragma unroll
    for (int r = 0; r < 32; r += 8)
        o[(size_t)(bx + ty + r) * HIDDEN + by + tx] = __float2half_rn(t[tx][ty + r]);
}

// ===================== pipelined mma.sync GEMM (R14 winner, unchanged) =====================
#define BM 128
#define BN 128
#define BK 64
#define NSTG 3
#define NKT  (HIDDEN / BK)             // 32
#define TILE_A   (BM * 128)            // 16384 B
#define TILE_B   (BN * 128)            // 16384 B
#define STG_BYTES (TILE_A + TILE_B)    // 32768
#define GEMM_SMEM (NSTG * STG_BYTES)   // 98304

__device__ __forceinline__ void load_quarter(uint32_t as, uint32_t bs,
                                             const __half* __restrict__ Arow,
                                             const __half* __restrict__ Brow,
                                             int kt, int tid, int q) {
    const __half* a = Arow + kt * BK;
    const __half* b = Brow + kt * BK;
    #pragma unroll
    for (int j = 0; j < 2; j++) {
        int c = q * 256 + tid + j * 128;
        int r = c >> 3, k16 = c & 7;
        uint32_t off = (uint32_t)(r * 128 + k16 * 16);
        CP_ASYNC16(as + SWZ(off), (const char*)(a + (size_t)r * HIDDEN) + k16 * 16);
    }
    #pragma unroll
    for (int j = 0; j < 2; j++) {
        int c = q * 256 + tid + j * 128;
        int r = c >> 3, k16 = c & 7;
        uint32_t off = (uint32_t)(r * 128 + k16 * 16);
        CP_ASYNC16(bs + SWZ(off), (const char*)(b + (size_t)r * HIDDEN) + k16 * 16);
    }
}

template<bool QKV>
__global__ __launch_bounds__(128, 2) void gemm_mma(const __half* __restrict__ A,
                                                   const __half* __restrict__ BW,
                                                   void* __restrict__ Cout) {
    extern __shared__ char smem[];
    uint32_t sb = smem_u32(smem);
    int tid = threadIdx.x;
    int wid = tid >> 5, lane = tid & 31;
    int warp_m = (wid >> 1) * 64;      // 0 or 64
    int warp_n = (wid & 1) * 64;       // 0 or 64
    int m0 = blockIdx.y * BM;
    int n0 = blockIdx.x * BN;

    const __half* Arow = A + (size_t)m0 * HIDDEN;
    const __half* Brow;
    if (QKV) Brow = BW + ((size_t)(n0 >> 11) << 22) + (size_t)(n0 & 2047) * HIDDEN;
    else     Brow = BW + (size_t)n0 * HIDDEN;

    float acc[4][8][4];
    #pragma unroll
    for (int mt = 0; mt < 4; mt++)
        #pragma unroll
        for (int nt = 0; nt < 8; nt++)
            #pragma unroll
            for (int z = 0; z < 4; z++) acc[mt][nt][z] = 0.f;

    #pragma unroll
    for (int s = 0; s < NSTG - 1; s++) {
        uint32_t base = sb + s * STG_BYTES;
        #pragma unroll
        for (int q = 0; q < 4; q++)
            load_quarter(base, base + TILE_A, Arow, Brow, s, tid, q);
        CP_COMMIT();
    }

    int a_row  = warp_m + (lane & 15);             // + mt*16
    int a_kg   = (lane >> 4) * 16;                 // 0 or 16 bytes
    int b_row4 = warp_n + (lane & 7) + ((lane >> 4) << 3);   // + ntp*16
    int b_kg4  = ((lane >> 3) & 1) * 16;

    for (int i = 0; i < NKT; i++) {
        int s = i % NSTG;
        CP_WAIT1();
        __syncthreads();

        int ip = i + NSTG - 1;
        int sn = ip % NSTG;
        uint32_t pbase = sb + sn * STG_BYTES;
        bool do_pf = (ip < NKT);

        uint32_t as_base = sb + s * STG_BYTES;
        uint32_t bs_base = as_base + TILE_A;

        #pragma unroll
        for (int ks = 0; ks < 4; ks++) {
            uint32_t a_frag[4][4];
            uint32_t b_frag[8][2];
            #pragma unroll
            for (int mt = 0; mt < 4; mt++) {
                uint32_t off = (uint32_t)((a_row + mt * 16) * 128 + ks * 32 + a_kg);
                LDSM_X4(a_frag[mt][0], a_frag[mt][1], a_frag[mt][2], a_frag[mt][3],
                        as_base + SWZ(off));
            }
            #pragma unroll
            for (int ntp = 0; ntp < 4; ntp++) {
                uint32_t off = (uint32_t)((b_row4 + ntp * 16) * 128 + ks * 32 + b_kg4);
                LDSM_X4(b_frag[2*ntp][0], b_frag[2*ntp][1],
                        b_frag[2*ntp+1][0], b_frag[2*ntp+1][1],
                        bs_base + SWZ(off));
            }
            if (do_pf) load_quarter(pbase, pbase + TILE_A, Arow, Brow, ip, tid, ks);

            #pragma unroll
            for (int mt = 0; mt < 4; mt++)
                #pragma unroll
                for (int nt = 0; nt < 8; nt++)
                    MMA16816(acc[mt][nt],
                             a_frag[mt][0], a_frag[mt][1], a_frag[mt][2], a_frag[mt][3],
                             b_frag[nt][0], b_frag[nt][1]);
        }
        CP_COMMIT();
    }

    int r_base = m0 + warp_m + (lane >> 2);
    int c_base = n0 + warp_n + (lane & 3) * 2;
    #pragma unroll
    for (int mt = 0; mt < 4; mt++) {
        #pragma unroll
        for (int nt = 0; nt < 8; nt++) {
            int row0 = r_base + mt * 16;
            int col  = c_base + nt * 8;
            if (QKV) {
                __half* d0 = (__half*)Cout + (size_t)row0 * (3 * HIDDEN) + col;
                __half* d1 = d0 + (size_t)8 * (3 * HIDDEN);
                *(__half2*)d0 = __floats2half2_rn(acc[mt][nt][0], acc[mt][nt][1]);
                *(__half2*)d1 = __floats2half2_rn(acc[mt][nt][2], acc[mt][nt][3]);
            } else {
                float* d0 = (float*)Cout + (size_t)row0 * HIDDEN + col;
                float* d1 = d0 + (size_t)8 * HIDDEN;
                *(float2*)d0 = make_float2(acc[mt][nt][0], acc[mt][nt][1]);
                *(float2*)d1 = make_float2(acc[mt][nt][2], acc[mt][nt][3]);
            }
        }
    }
}

// ===================== per-token RoPE + 32x32 head-attention (R14 winner, + tok0) =====================
#define AROW 33   // half2 per row

__global__ __launch_bounds__(128) void attn_kernel(int tok0) {
    int t = tok0 + blockIdx.x;
    int s = t & (SEQ - 1);
    int tid = threadIdx.x;

    __shared__ __half2 qs[32 * AROW], ks[32 * AROW], vs[32 * AROW];
    __shared__ float ss[32][33];
    __shared__ float cosv[32], sinv[32];

    if (tid < 32) {
        float e = (float)(2 * tid) / 64.0f;
        float p = powf(10000.0f, e);
        float ang = (float)s * (1.0f / p);
        sinv[tid] = sinf(ang);
        cosv[tid] = cosf(ang);
    }
    __syncthreads();

    const __half* qg = g_qkv + (size_t)t * (3 * HIDDEN);
    const __half* kg = qg + HIDDEN;
    const __half* vg = qg + 2 * HIDDEN;

    #pragma unroll
    for (int it = 0; it < 8; it++) {
        int idx2 = tid + it * 128;           // 0..1023 half2 index
        int h = idx2 >> 5, d2 = idx2 & 31;
        float c = cosv[h], sn = sinv[h];
        int d0 = 2 * d2, d1 = d0 + 1;
        int p0 = (d0 < 32) ? (2 * d0 + 1) : (2 * (d0 - 32));
        float sg0 = (d0 < 32) ? -1.0f : 1.0f;
        int p1 = (d1 < 32) ? (2 * d1 + 1) : (2 * (d1 - 32));
        float sg1 = (d1 < 32) ? -1.0f : 1.0f;
        int base = h * 64;

        float q0 = __half2float(qg[base + d0]), q0p = __half2float(qg[base + p0]);
        float q1 = __half2float(qg[base + d1]), q1p = __half2float(qg[base + p1]);
        qs[h * AROW + d2] = __floats2half2_rn(q0 * c + sg0 * q0p * sn, q1 * c + sg1 * q1p * sn);

        float k0 = __half2float(kg[base + d0]), k0p = __half2float(kg[base + p0]);
        float k1 = __half2float(kg[base + d1]), k1p = __half2float(kg[base + p1]);
        ks[h * AROW + d2] = __floats2half2_rn(k0 * c + sg0 * k0p * sn, k1 * c + sg1 * k1p * sn);

        vs[h * AROW + d2] = *(const __half2*)(vg + base + d0);
    }
    __syncthreads();

    {
        int i  = tid >> 2;
        int j0 = (tid & 3) * 8;
        const __half2* qrow = qs + i * AROW;
        float acc[8] = {0,0,0,0,0,0,0,0};
        #pragma unroll
        for (int d2 = 0; d2 < 32; d2++) {
            float2 qf = __half22float2(qrow[d2]);
            #pragma unroll
            for (int jj = 0; jj < 8; jj++) {
                float2 kf = __half22float2(ks[(j0 + jj) * AROW + d2]);
                acc[jj] += qf.x * kf.x + qf.y * kf.y;
            }
        }
        #pragma unroll
        for (int jj = 0; jj < 8; jj++)
            ss[i][j0 + jj] = acc[jj] * 0.125f;   // 1/sqrt(64)
    }
    __syncthreads();

    if (tid < 32) {
        float mx = -1e30f;
        #pragma unroll
        for (int j = 0; j < 32; j++) mx = fmaxf(mx, ss[tid][j]);
        float sum = 0.f;
        #pragma unroll
        for (int j = 0; j < 32; j++) {
            float e = expf(ss[tid][j] - mx);
            ss[tid][j] = e;
            sum += e;
        }
        float inv = 1.0f / sum;
        #pragma unroll
        for (int j = 0; j < 32; j++) ss[tid][j] *= inv;
    }
    __syncthreads();

    {
        int i   = tid >> 2;
        int dd0 = (tid & 3) * 8;                 // half2 offset within row
        float2 acc[8];
        #pragma unroll
        for (int z = 0; z < 8; z++) acc[z] = make_float2(0.f, 0.f);
        #pragma unroll
        for (int j = 0; j < 32; j++) {
            float p = ss[i][j];
            const __half2* vrow = vs + j * AROW + dd0;
            #pragma unroll
            for (int z = 0; z < 8; z++) {
                float2 vf = __half22float2(vrow[z]);
                acc[z].x += p * vf.x;
                acc[z].y += p * vf.y;
            }
        }
        __half* og = g_attn + (size_t)t * HIDDEN + i * 64 + dd0 * 2;
        #pragma unroll
        for (int z = 0; z < 8; z += 4) {
            __align__(16) __half2 o[4];
            o[0] = __floats2half2_rn(acc[z+0].x, acc[z+0].y);
            o[1] = __floats2half2_rn(acc[z+1].x, acc[z+1].y);
            o[2] = __floats2half2_rn(acc[z+2].x, acc[z+2].y);
            o[3] = __floats2half2_rn(acc[z+3].x, acc[z+3].y);
            *(uint4*)(og + z * 2) = *(const uint4*)o;
        }
    }
}

// ===================== launch (fork-join pipeline, light attn) =====================
extern "C" void kernel_launch(void* const* d_in, const int* in_sizes, int n_in,
                              void* d_out, int out_size) {
    const float* hs    = (const float*)d_in[0];
    const float* w_q   = (const float*)d_in[1];
    const float* w_k   = (const float*)d_in[2];
    const float* w_v   = (const float*)d_in[3];
    const float* w_o   = (const float*)d_in[4];
    const float* gamma = (const float*)d_in[5];
    const float* beta  = (const float*)d_in[6];

    __half *xdev, *wtdev, *qkvdev, *attndev;
    cudaGetSymbolAddress((void**)&xdev, g_x);
    cudaGetSymbolAddress((void**)&wtdev, g_wt);
    cudaGetSymbolAddress((void**)&qkvdev, g_qkv);
    cudaGetSymbolAddress((void**)&attndev, g_attn);

    cudaFuncSetAttribute(gemm_mma<true>,  cudaFuncAttributeMaxDynamicSharedMemorySize, GEMM_SMEM);
    cudaFuncSetAttribute(gemm_mma<false>, cudaFuncAttributeMaxDynamicSharedMemorySize, GEMM_SMEM);

    cudaStream_t s0 = 0;            // capture-origin (default) stream
    cudaStream_t s2 = g_infra.s2;   // helper stream

    // fork: weight convert on s2, concurrent with LN on s0
    cudaEventRecord(g_infra.eFork, s0);
    cudaStreamWaitEvent(s2, g_infra.eFork, 0);
    {
        dim3 grid(HIDDEN / 32, HIDDEN / 32, 4);
        cvt_t4_kernel<<<grid, 256, 0, s2>>>(w_q, w_k, w_v, w_o, wtdev);
        cudaEventRecord(g_infra.eCvt, s2);
    }
    ln_kernel<<<NTOK, 256, 0, s0>>>(hs, gamma, beta);
    cudaStreamWaitEvent(s0, g_infra.eCvt, 0);    // qkv needs weights

    // QKV GEMM chunk 0 (tokens 0..MCHUNK)
    {
        dim3 grid(3 * HIDDEN / BN, MCHUNK / BM);   // (48, 128)
        gemm_mma<true><<<grid, 128, GEMM_SMEM, s0>>>(xdev, wtdev, qkvdev);
        cudaEventRecord(g_infra.eQ0, s0);
    }
    // attn chunk 0 on s2 overlaps QKV chunk 1 on s0
    cudaStreamWaitEvent(s2, g_infra.eQ0, 0);
    attn_kernel<<<MCHUNK, 128, 0, s2>>>(0);
    cudaEventRecord(g_infra.eA0, s2);
    {
        dim3 grid(3 * HIDDEN / BN, MCHUNK / BM);
        gemm_mma<true><<<grid, 128, GEMM_SMEM, s0>>>(xdev + (size_t)MCHUNK * HIDDEN, wtdev,
                                                     qkvdev + (size_t)MCHUNK * 3 * HIDDEN);
        cudaEventRecord(g_infra.eQ1, s0);
    }
    // attn chunk 1 on s2 overlaps out-GEMM chunk 0 on s0
    cudaStreamWaitEvent(s2, g_infra.eQ1, 0);
    attn_kernel<<<MCHUNK, 128, 0, s2>>>(MCHUNK);
    cudaEventRecord(g_infra.eA1, s2);

    cudaStreamWaitEvent(s0, g_infra.eA0, 0);
    {
        dim3 grid(HIDDEN / BN, MCHUNK / BM);       // (16, 128)
        gemm_mma<false><<<grid, 128, GEMM_SMEM, s0>>>(attndev, wtdev + 3 * (size_t)HIDDEN * HIDDEN, d_out);
    }
    cudaStreamWaitEvent(s0, g_infra.eA1, 0);       // join s2 before final chunk
    {
        dim3 grid(HIDDEN / BN, MCHUNK / BM);
        gemm_mma<false><<<grid, 128, GEMM_SMEM, s0>>>(attndev + (size_t)MCHUNK * HIDDEN,
                                                      wtdev + 3 * (size_t)HIDDEN * HIDDEN,
                                                      (float*)d_out + (size_t)MCHUNK * HIDDEN);
    }
}

// round 17
// speedup vs baseline: 1.1490x; 1.1490x over previous
#include <cuda_runtime.h>
#include <cuda_fp16.h>
#include <stdint.h>

#define HIDDEN   2048
#define NHEADS   32
#define SEQ      4096
#define NTOK     32768           // B * S

// ---------------- scratch (static device globals; no allocation) ----------------
__device__ __half g_x[(size_t)NTOK * HIDDEN];              // LN output fp16     (128 MB)
__device__ __half g_wt[(size_t)4 * HIDDEN * HIDDEN];       // wq^T|wk^T|wv^T|wo^T fp16 (32 MB)
__device__ __half g_qkv[(size_t)NTOK * 3 * HIDDEN];        // q|k|v per token    (402 MB)
__device__ __half g_attn[(size_t)NTOK * HIDDEN];           // attn out fp16      (128 MB)

// ===================== PTX helpers (baseline sm_80+ features only) =====================
__device__ __forceinline__ uint32_t smem_u32(const void* p) {
    uint32_t a;
    asm("{ .reg .u64 t; cvta.to.shared.u64 t, %1; cvt.u32.u64 %0, t; }" : "=r"(a) : "l"(p));
    return a;
}
#define CP_ASYNC16(dst, src) \
    asm volatile("cp.async.cg.shared.global [%0], [%1], 16;" :: "r"(dst), "l"(src) : "memory")
#define CP_COMMIT() asm volatile("cp.async.commit_group;" ::: "memory")
#define CP_WAIT1()  asm volatile("cp.async.wait_group 1;" ::: "memory")

#define LDSM_X4(r0,r1,r2,r3, addr) \
    asm volatile("ldmatrix.sync.aligned.m8n8.x4.shared.b16 {%0,%1,%2,%3}, [%4];" \
        : "=r"(r0),"=r"(r1),"=r"(r2),"=r"(r3) : "r"(addr))
#define LDSM_X4_T(r0,r1,r2,r3, addr) \
    asm volatile("ldmatrix.sync.aligned.m8n8.x4.trans.shared.b16 {%0,%1,%2,%3}, [%4];" \
        : "=r"(r0),"=r"(r1),"=r"(r2),"=r"(r3) : "r"(addr))

#define MMA16816(d, a0,a1,a2,a3, b0,b1) \
    asm volatile("mma.sync.aligned.m16n8k16.row.col.f32.f16.f16.f32 " \
        "{%0,%1,%2,%3}, {%4,%5,%6,%7}, {%8,%9}, {%0,%1,%2,%3};" \
        : "+f"((d)[0]),"+f"((d)[1]),"+f"((d)[2]),"+f"((d)[3]) \
        : "r"(a0),"r"(a1),"r"(a2),"r"(a3), "r"(b0),"r"(b1))

#define SWZ(off) ((off) ^ (((off) >> 3) & 0x70))

// ===================== LayerNorm -> fp16 =====================
__device__ __forceinline__ float warp_red(float v) {
    #pragma unroll
    for (int o = 16; o; o >>= 1) v += __shfl_xor_sync(0xffffffffu, v, o);
    return v;
}

__global__ __launch_bounds__(256) void ln_kernel(const float* __restrict__ hs,
                          const float* __restrict__ gamma,
                          const float* __restrict__ beta) {
    int t = blockIdx.x;
    int tid = threadIdx.x;
    const float4* row = (const float4*)(hs + (size_t)t * HIDDEN);
    float4 v0 = row[tid];
    float4 v1 = row[tid + 256];
    float s = v0.x + v0.y + v0.z + v0.w + v1.x + v1.y + v1.z + v1.w;
    float q = v0.x*v0.x + v0.y*v0.y + v0.z*v0.z + v0.w*v0.w
            + v1.x*v1.x + v1.y*v1.y + v1.z*v1.z + v1.w*v1.w;
    s = warp_red(s);
    q = warp_red(q);
    __shared__ float sh_s[8], sh_q[8];
    int w = tid >> 5, l = tid & 31;
    if (l == 0) { sh_s[w] = s; sh_q[w] = q; }
    __syncthreads();
    float st = 0.f, qt = 0.f;
    #pragma unroll
    for (int i = 0; i < 8; i++) { st += sh_s[i]; qt += sh_q[i]; }
    float mean = st * (1.0f / HIDDEN);
    float var  = qt * (1.0f / HIDDEN) - mean * mean;
    float rstd = rsqrtf(var + 1e-5f);

    const float4* g4 = (const float4*)gamma;
    const float4* b4 = (const float4*)beta;
    __half2* out = (__half2*)(g_x + (size_t)t * HIDDEN);
    {
        float4 g = g4[tid], b = b4[tid];
        out[2*tid]   = __floats2half2_rn((v0.x - mean)*rstd*g.x + b.x, (v0.y - mean)*rstd*g.y + b.y);
        out[2*tid+1] = __floats2half2_rn((v0.z - mean)*rstd*g.z + b.z, (v0.w - mean)*rstd*g.w + b.w);
    }
    {
        int i2 = tid + 256;
        float4 g = g4[i2], b = b4[i2];
        out[2*i2]   = __floats2half2_rn((v1.x - mean)*rstd*g.x + b.x, (v1.y - mean)*rstd*g.y + b.y);
        out[2*i2+1] = __floats2half2_rn((v1.z - mean)*rstd*g.z + b.z, (v1.w - mean)*rstd*g.w + b.w);
    }
}

// ===================== weight fp32 -> fp16, transposed (2 matrices per launch) =====================
__global__ __launch_bounds__(256) void cvt_t2_kernel(const float* __restrict__ wa, __half* __restrict__ oa,
                                                     const float* __restrict__ wb, __half* __restrict__ ob) {
    const float* w = (blockIdx.z == 0) ? wa : wb;
    __half*      o = (blockIdx.z == 0) ? oa : ob;
    __shared__ float t[32][33];
    int bx = blockIdx.x * 32;   // n0
    int by = blockIdx.y * 32;   // k0
    int tx = threadIdx.x & 31, ty = threadIdx.x >> 5;
    #pragma unroll
    for (int r = 0; r < 32; r += 8)
        t[ty + r][tx] = w[(size_t)(by + ty + r) * HIDDEN + bx + tx];
    __syncthreads();
    #pragma unroll
    for (int r = 0; r < 32; r += 8)
        o[(size_t)(bx + ty + r) * HIDDEN + by + tx] = __float2half_rn(t[tx][ty + r]);
}

// ===================== pipelined mma.sync GEMM (R14 winner, unchanged) =====================
#define BM 128
#define BN 128
#define BK 64
#define NSTG 3
#define NKT  (HIDDEN / BK)             // 32
#define TILE_A   (BM * 128)            // 16384 B
#define TILE_B   (BN * 128)            // 16384 B
#define STG_BYTES (TILE_A + TILE_B)    // 32768
#define GEMM_SMEM (NSTG * STG_BYTES)   // 98304

__device__ __forceinline__ void load_quarter(uint32_t as, uint32_t bs,
                                             const __half* __restrict__ Arow,
                                             const __half* __restrict__ Brow,
                                             int kt, int tid, int q) {
    const __half* a = Arow + kt * BK;
    const __half* b = Brow + kt * BK;
    #pragma unroll
    for (int j = 0; j < 2; j++) {
        int c = q * 256 + tid + j * 128;
        int r = c >> 3, k16 = c & 7;
        uint32_t off = (uint32_t)(r * 128 + k16 * 16);
        CP_ASYNC16(as + SWZ(off), (const char*)(a + (size_t)r * HIDDEN) + k16 * 16);
    }
    #pragma unroll
    for (int j = 0; j < 2; j++) {
        int c = q * 256 + tid + j * 128;
        int r = c >> 3, k16 = c & 7;
        uint32_t off = (uint32_t)(r * 128 + k16 * 16);
        CP_ASYNC16(bs + SWZ(off), (const char*)(b + (size_t)r * HIDDEN) + k16 * 16);
    }
}

template<bool QKV>
__global__ __launch_bounds__(128, 2) void gemm_mma(const __half* __restrict__ A,
                                                   const __half* __restrict__ BW,
                                                   void* __restrict__ Cout) {
    extern __shared__ char smem[];
    uint32_t sb = smem_u32(smem);
    int tid = threadIdx.x;
    int wid = tid >> 5, lane = tid & 31;
    int warp_m = (wid >> 1) * 64;      // 0 or 64
    int warp_n = (wid & 1) * 64;       // 0 or 64
    int m0 = blockIdx.y * BM;
    int n0 = blockIdx.x * BN;

    const __half* Arow = A + (size_t)m0 * HIDDEN;
    const __half* Brow;
    if (QKV) Brow = BW + ((size_t)(n0 >> 11) << 22) + (size_t)(n0 & 2047) * HIDDEN;
    else     Brow = BW + (size_t)n0 * HIDDEN;

    float acc[4][8][4];
    #pragma unroll
    for (int mt = 0; mt < 4; mt++)
        #pragma unroll
        for (int nt = 0; nt < 8; nt++)
            #pragma unroll
            for (int z = 0; z < 4; z++) acc[mt][nt][z] = 0.f;

    #pragma unroll
    for (int s = 0; s < NSTG - 1; s++) {
        uint32_t base = sb + s * STG_BYTES;
        #pragma unroll
        for (int q = 0; q < 4; q++)
            load_quarter(base, base + TILE_A, Arow, Brow, s, tid, q);
        CP_COMMIT();
    }

    int a_row  = warp_m + (lane & 15);             // + mt*16
    int a_kg   = (lane >> 4) * 16;                 // 0 or 16 bytes
    int b_row4 = warp_n + (lane & 7) + ((lane >> 4) << 3);   // + ntp*16
    int b_kg4  = ((lane >> 3) & 1) * 16;

    for (int i = 0; i < NKT; i++) {
        int s = i % NSTG;
        CP_WAIT1();
        __syncthreads();

        int ip = i + NSTG - 1;
        int sn = ip % NSTG;
        uint32_t pbase = sb + sn * STG_BYTES;
        bool do_pf = (ip < NKT);

        uint32_t as_base = sb + s * STG_BYTES;
        uint32_t bs_base = as_base + TILE_A;

        #pragma unroll
        for (int ks = 0; ks < 4; ks++) {
            uint32_t a_frag[4][4];
            uint32_t b_frag[8][2];
            #pragma unroll
            for (int mt = 0; mt < 4; mt++) {
                uint32_t off = (uint32_t)((a_row + mt * 16) * 128 + ks * 32 + a_kg);
                LDSM_X4(a_frag[mt][0], a_frag[mt][1], a_frag[mt][2], a_frag[mt][3],
                        as_base + SWZ(off));
            }
            #pragma unroll
            for (int ntp = 0; ntp < 4; ntp++) {
                uint32_t off = (uint32_t)((b_row4 + ntp * 16) * 128 + ks * 32 + b_kg4);
                LDSM_X4(b_frag[2*ntp][0], b_frag[2*ntp][1],
                        b_frag[2*ntp+1][0], b_frag[2*ntp+1][1],
                        bs_base + SWZ(off));
            }
            if (do_pf) load_quarter(pbase, pbase + TILE_A, Arow, Brow, ip, tid, ks);

            #pragma unroll
            for (int mt = 0; mt < 4; mt++)
                #pragma unroll
                for (int nt = 0; nt < 8; nt++)
                    MMA16816(acc[mt][nt],
                             a_frag[mt][0], a_frag[mt][1], a_frag[mt][2], a_frag[mt][3],
                             b_frag[nt][0], b_frag[nt][1]);
        }
        CP_COMMIT();
    }

    int r_base = m0 + warp_m + (lane >> 2);
    int c_base = n0 + warp_n + (lane & 3) * 2;
    #pragma unroll
    for (int mt = 0; mt < 4; mt++) {
        #pragma unroll
        for (int nt = 0; nt < 8; nt++) {
            int row0 = r_base + mt * 16;
            int col  = c_base + nt * 8;
            if (QKV) {
                __half* d0 = (__half*)Cout + (size_t)row0 * (3 * HIDDEN) + col;
                __half* d1 = d0 + (size_t)8 * (3 * HIDDEN);
                *(__half2*)d0 = __floats2half2_rn(acc[mt][nt][0], acc[mt][nt][1]);
                *(__half2*)d1 = __floats2half2_rn(acc[mt][nt][2], acc[mt][nt][3]);
            } else {
                float* d0 = (float*)Cout + (size_t)row0 * HIDDEN + col;
                float* d1 = d0 + (size_t)8 * HIDDEN;
                *(float2*)d0 = make_float2(acc[mt][nt][0], acc[mt][nt][1]);
                *(float2*)d1 = make_float2(acc[mt][nt][2], acc[mt][nt][3]);
            }
        }
    }
}

// ===================== tensor-core RoPE + 32x32 head-attention =====================
// 1 warp per token; block = 4 warps; 16KB smem/token:
//   Q̂: 32 rows x 72 halfs (2304 h), K̂: 2304 h, V: 2304 h, P: 32 x 40 halfs (1280 h) = 8192 halfs
// lane = head for RoPE (cos/sin per lane; partner elements intra-row, in registers).
// Q̂ pre-scaled by 1/sqrt(64).
#define QK_STR 72   // halfs
#define P_STR  40   // halfs

__global__ __launch_bounds__(128, 3) void attn_mma_kernel() {
    extern __shared__ __half smh[];
    int wid = threadIdx.x >> 5, lane = threadIdx.x & 31;
    int t = blockIdx.x * 4 + wid;
    int spos = t & (SEQ - 1);

    __half* Qs = smh + wid * 8192;
    __half* Ks = Qs + 2304;
    __half* Vs = Qs + 4608;
    __half* Ps = Qs + 6912;
    uint32_t q_sm = smem_u32(Qs);
    uint32_t k_sm = smem_u32(Ks);
    uint32_t v_sm = smem_u32(Vs);
    uint32_t p_sm = smem_u32(Ps);

    // per-lane RoPE params (lane = head), same math as R14
    float e  = (float)(2 * lane) / 64.0f;
    float pw = powf(10000.0f, e);
    float ang = (float)spos * (1.0f / pw);
    float sn = sinf(ang), cs = cosf(ang);

    const __half* gq = g_qkv + (size_t)t * (3 * HIDDEN) + lane * 64;

    // ---- RoPE Q (scale 0.125 folded) and K into smem ----
    #pragma unroll
    for (int mat = 0; mat < 2; mat++) {
        const __half* src = gq + mat * HIDDEN;      // q then k
        __half* dst = (mat == 0) ? Qs : Ks;
        float cc = (mat == 0) ? cs * 0.125f : cs;
        float ssn = (mat == 0) ? sn * 0.125f : sn;
        uint32_t r[32];
        #pragma unroll
        for (int i = 0; i < 8; i++) {
            uint4 u = *(const uint4*)(src + i * 8);
            r[4*i] = u.x; r[4*i+1] = u.y; r[4*i+2] = u.z; r[4*i+3] = u.w;
        }
        #pragma unroll
        for (int d2 = 0; d2 < 32; d2++) {
            float2 v = __half22float2(*(__half2*)&r[d2]);
            float res0, res1;
            if (d2 < 16) {
                float p0 = __half2float(((__half2*)&r[2*d2])->y);      // elem 4d2+1
                float p1 = __half2float(((__half2*)&r[2*d2+1])->y);    // elem 4d2+3
                res0 = v.x * cc - p0 * ssn;
                res1 = v.y * cc - p1 * ssn;
            } else {
                float p0 = __half2float(((__half2*)&r[2*d2-32])->x);   // elem 4d2-64
                float p1 = __half2float(((__half2*)&r[2*d2-31])->x);   // elem 4d2-62
                res0 = v.x * cc + p0 * ssn;
                res1 = v.y * cc + p1 * ssn;
            }
            *(__half2*)(dst + lane * QK_STR + 2 * d2) = __floats2half2_rn(res0, res1);
        }
    }
    // ---- V: coalesced copy into stride-72 smem ----
    {
        const __half* gv = gq - lane * 64 + 2 * HIDDEN;
        #pragma unroll
        for (int j = 0; j < 8; j++) {
            int c = lane + j * 32;           // 16B chunk id (256 total)
            int row = c >> 3, col = (c & 7) * 8;
            uint4 u = *(const uint4*)(gv + row * 64 + col);
            *(uint4*)(Vs + row * QK_STR + col) = u;
        }
    }
    __syncwarp();

    int a_row = lane & 15;
    int a_k8  = (lane >> 4) * 8;                     // halfs
    int b_row = (lane & 7) + ((lane >> 4) << 3);     // + ntp*16
    int b_k8  = ((lane >> 3) & 1) * 8;               // halfs

    // ---- scores = Q̂ K̂^T (pre-scaled) ----
    float sc[2][4][4];
    #pragma unroll
    for (int mt = 0; mt < 2; mt++)
        #pragma unroll
        for (int nt = 0; nt < 4; nt++)
            #pragma unroll
            for (int z = 0; z < 4; z++) sc[mt][nt][z] = 0.f;

    #pragma unroll
    for (int kc = 0; kc < 4; kc++) {
        uint32_t af[2][4], bf[4][2];
        #pragma unroll
        for (int mt = 0; mt < 2; mt++)
            LDSM_X4(af[mt][0], af[mt][1], af[mt][2], af[mt][3],
                    q_sm + (uint32_t)(((mt*16 + a_row) * QK_STR + kc*16 + a_k8) * 2));
        #pragma unroll
        for (int ntp = 0; ntp < 2; ntp++)
            LDSM_X4(bf[2*ntp][0], bf[2*ntp][1], bf[2*ntp+1][0], bf[2*ntp+1][1],
                    k_sm + (uint32_t)(((ntp*16 + b_row) * QK_STR + kc*16 + b_k8) * 2));
        #pragma unroll
        for (int mt = 0; mt < 2; mt++)
            #pragma unroll
            for (int nt = 0; nt < 4; nt++)
                MMA16816(sc[mt][nt], af[mt][0], af[mt][1], af[mt][2], af[mt][3],
                         bf[nt][0], bf[nt][1]);
    }

    // ---- softmax on c-frags; write P (fp16) ----
    #pragma unroll
    for (int mt = 0; mt < 2; mt++) {
        float m1 = -1e30f, m2 = -1e30f;
        #pragma unroll
        for (int nt = 0; nt < 4; nt++) {
            m1 = fmaxf(m1, fmaxf(sc[mt][nt][0], sc[mt][nt][1]));
            m2 = fmaxf(m2, fmaxf(sc[mt][nt][2], sc[mt][nt][3]));
        }
        m1 = fmaxf(m1, __shfl_xor_sync(0xffffffffu, m1, 1));
        m1 = fmaxf(m1, __shfl_xor_sync(0xffffffffu, m1, 2));
        m2 = fmaxf(m2, __shfl_xor_sync(0xffffffffu, m2, 1));
        m2 = fmaxf(m2, __shfl_xor_sync(0xffffffffu, m2, 2));
        float s1 = 0.f, s2 = 0.f;
        #pragma unroll
        for (int nt = 0; nt < 4; nt++) {
            sc[mt][nt][0] = __expf(sc[mt][nt][0] - m1);
            sc[mt][nt][1] = __expf(sc[mt][nt][1] - m1);
            sc[mt][nt][2] = __expf(sc[mt][nt][2] - m2);
            sc[mt][nt][3] = __expf(sc[mt][nt][3] - m2);
            s1 += sc[mt][nt][0] + sc[mt][nt][1];
            s2 += sc[mt][nt][2] + sc[mt][nt][3];
        }
        s1 += __shfl_xor_sync(0xffffffffu, s1, 1);
        s1 += __shfl_xor_sync(0xffffffffu, s1, 2);
        s2 += __shfl_xor_sync(0xffffffffu, s2, 1);
        s2 += __shfl_xor_sync(0xffffffffu, s2, 2);
        float i1 = 1.0f / s1, i2 = 1.0f / s2;
        int r1 = mt * 16 + (lane >> 2);
        int cb = 2 * (lane & 3);
        #pragma unroll
        for (int nt = 0; nt < 4; nt++) {
            *(__half2*)(Ps + r1 * P_STR + nt * 8 + cb) =
                __floats2half2_rn(sc[mt][nt][0] * i1, sc[mt][nt][1] * i1);
            *(__half2*)(Ps + (r1 + 8) * P_STR + nt * 8 + cb) =
                __floats2half2_rn(sc[mt][nt][2] * i2, sc[mt][nt][3] * i2);
        }
    }
    __syncwarp();

    // ---- out = P V ----
    float oc[2][8][4];
    #pragma unroll
    for (int mt = 0; mt < 2; mt++)
        #pragma unroll
        for (int nt = 0; nt < 8; nt++)
            #pragma unroll
            for (int z = 0; z < 4; z++) oc[mt][nt][z] = 0.f;

    int vrow = (lane & 7) + ((lane >> 3) & 1) * 8;   // + kc*16
    int vcol = (lane >> 4) * 8;                      // + np*16
    #pragma unroll
    for (int kc = 0; kc < 2; kc++) {
        uint32_t af[2][4], bf[8][2];
        #pragma unroll
        for (int mt = 0; mt < 2; mt++)
            LDSM_X4(af[mt][0], af[mt][1], af[mt][2], af[mt][3],
                    p_sm + (uint32_t)(((mt*16 + a_row) * P_STR + kc*16 + a_k8) * 2));
        #pragma unroll
        for (int np = 0; np < 4; np++)
            LDSM_X4_T(bf[2*np][0], bf[2*np][1], bf[2*np+1][0], bf[2*np+1][1],
                      v_sm + (uint32_t)(((kc*16 + vrow) * QK_STR + np*16 + vcol) * 2));
        #pragma unroll
        for (int mt = 0; mt < 2; mt++)
            #pragma unroll
            for (int nt = 0; nt < 8; nt++)
                MMA16816(oc[mt][nt], af[mt][0], af[mt][1], af[mt][2], af[mt][3],
                         bf[nt][0], bf[nt][1]);
    }

    // ---- epilogue: c-frags -> g_attn fp16 ----
    __half* og = g_attn + (size_t)t * HIDDEN;
    int cb = 2 * (lane & 3);
    #pragma unroll
    for (int mt = 0; mt < 2; mt++) {
        int r1 = mt * 16 + (lane >> 2);
        #pragma unroll
        for (int nt = 0; nt < 8; nt++) {
            int col = nt * 8 + cb;
            *(__half2*)(og + r1 * 64 + col) = __floats2half2_rn(oc[mt][nt][0], oc[mt][nt][1]);
            *(__half2*)(og + (r1 + 8) * 64 + col) = __floats2half2_rn(oc[mt][nt][2], oc[mt][nt][3]);
        }
    }
}

// ===================== launch (serial, 6 launches) =====================
extern "C" void kernel_launch(void* const* d_in, const int* in_sizes, int n_in,
                              void* d_out, int out_size) {
    const float* hs    = (const float*)d_in[0];
    const float* w_q   = (const float*)d_in[1];
    const float* w_k   = (const float*)d_in[2];
    const float* w_v   = (const float*)d_in[3];
    const float* w_o   = (const float*)d_in[4];
    const float* gamma = (const float*)d_in[5];
    const float* beta  = (const float*)d_in[6];

    __half *xdev, *wtdev, *qkvdev, *attndev;
    cudaGetSymbolAddress((void**)&xdev, g_x);
    cudaGetSymbolAddress((void**)&wtdev, g_wt);
    cudaGetSymbolAddress((void**)&qkvdev, g_qkv);
    cudaGetSymbolAddress((void**)&attndev, g_attn);

    cudaFuncSetAttribute(gemm_mma<true>,  cudaFuncAttributeMaxDynamicSharedMemorySize, GEMM_SMEM);
    cudaFuncSetAttribute(gemm_mma<false>, cudaFuncAttributeMaxDynamicSharedMemorySize, GEMM_SMEM);
    cudaFuncSetAttribute(attn_mma_kernel, cudaFuncAttributeMaxDynamicSharedMemorySize, 65536);

    // 1) LayerNorm -> fp16            (launch 0)
    ln_kernel<<<NTOK, 256>>>(hs, gamma, beta);

    // 2) weights: fp32 -> fp16 transposed (launches 1,2)
    {
        dim3 grid(HIDDEN / 32, HIDDEN / 32, 2);
        cvt_t2_kernel<<<grid, 256>>>(w_q, wtdev + 0 * (size_t)HIDDEN * HIDDEN,
                                     w_k, wtdev + 1 * (size_t)HIDDEN * HIDDEN);
        cvt_t2_kernel<<<grid, 256>>>(w_v, wtdev + 2 * (size_t)HIDDEN * HIDDEN,
                                     w_o, wtdev + 3 * (size_t)HIDDEN * HIDDEN);
    }

    // 3) QKV GEMM: [32768, 6144] fp16 (launch 3)
    {
        dim3 grid(3 * HIDDEN / BN, NTOK / BM);   // (48, 256)
        gemm_mma<true><<<grid, 128, GEMM_SMEM>>>(xdev, wtdev, qkvdev);
    }

    // 4) RoPE + head attention via tensor cores (launch 4)
    attn_mma_kernel<<<NTOK / 4, 128, 65536>>>();

    // 5) Output GEMM: [32768, 2048] fp32 -> d_out (launch 5)
    {
        dim3 grid(HIDDEN / BN, NTOK / BM);       // (16, 256)
        gemm_mma<false><<<grid, 128, GEMM_SMEM>>>(attndev, wtdev + 3 * (size_t)HIDDEN * HIDDEN, d_out);
    }
}